// round 15
// baseline (speedup 1.0000x reference)
#include <cuda_runtime.h>
#include <cuda_fp16.h>
#include <math.h>

#define Bn 16
#define Cn 192
#define HW 4096
#define CHW (Cn*HW)          // 786432
#define NPIX (Bn*CHW)        // 12582912
#define CPG 48
#define NGRP (CPG*HW)        // 196608

// Scratch (device globals: allocation-free rule)
__device__ __half g_zch[NPIX];           // depthwise conv output (fp16)
__device__ uint4 g_wfrag4[18432];        // fp16 fragment-packed weights
__device__ float g_part[Bn*Cn*2];        // per-channel (sum, sumsq)
__device__ float g_mu[64];
__device__ float g_rstd[64];

__device__ __forceinline__ unsigned smem_u32(const void* p){
    unsigned a;
    asm("{ .reg .u64 t; cvta.to.shared.u64 t, %1; cvt.u32.u64 %0, t; }"
        : "=r"(a) : "l"(p));
    return a;
}
__device__ __forceinline__ unsigned packh2(float lo, float hi){
    __half2 h = __floats2half2_rn(lo, hi);
    return *reinterpret_cast<unsigned*>(&h);
}
__device__ __forceinline__ float sigm_f(float v){
    return __fdividef(1.0f, 1.0f + __expf(-v));
}
__device__ __forceinline__ float tanh_f(float v){
    float a = __expf(2.0f*v);
    return 1.0f - __fdividef(2.0f, a + 1.0f);
}
__device__ __forceinline__ float gelu_exact(float v){
    return 0.5f*v*(1.0f + erff(v*0.70710678118654752f));
}
// fp16 m16n8k16 MMA, fp32 accumulate
__device__ __forceinline__ void mma_f16(float d[4], uint4 A, uint2 B){
    asm volatile("mma.sync.aligned.m16n8k16.row.col.f32.f16.f16.f32 "
        "{%0,%1,%2,%3}, {%4,%5,%6,%7}, {%8,%9}, {%0,%1,%2,%3};"
        : "+f"(d[0]), "+f"(d[1]), "+f"(d[2]), "+f"(d[3])
        : "r"(A.x), "r"(A.y), "r"(A.z), "r"(A.w), "r"(B.x), "r"(B.y));
}

// ---------------------------------------------------------------------------
// Kernel 1 (R15): conv (blocks < Bn*Cn) + weight packing (last 72 blocks).
// Conv: one block per (b,c) channel, 4x4 outputs/thread, fp16 out, fp32 stats.
// ---------------------------------------------------------------------------
__global__ __launch_bounds__(256) void conv_kernel(
    const float* __restrict__ x, const float* __restrict__ hid,
    const float* __restrict__ dww, const float* __restrict__ dwb,
    const float* __restrict__ pw)
{
    __shared__ __align__(16) float patch[70][72];   // 20160 B, px = gx+3
    __shared__ float wsm[49];
    __shared__ float redsum[8], redsq[8];

    int tid  = threadIdx.x;

    // --- weight-packing path (blocks Bn*Cn .. Bn*Cn+71) ---
    if (blockIdx.x >= Bn*Cn) {
        int i4 = (blockIdx.x - Bn*Cn)*256 + tid;     // 0..18431
        int chunk = i4 >> 8, j = i4 & 255;
        int seg12 = chunk / 6, c32 = chunk - seg12*6;
        int h = j >> 7, slot = (j >> 5) & 3, l = j & 31;
        int g = l >> 2, t = l & 3;
        int r  = seg12*64 + slot*16 + g;
        int k0 = c32*32 + h*16 + 2*t;
        #define WVAL(rr, kk) pw[(((rr) & 3)*192 + ((rr) >> 2))*192 + (kk)]
        unsigned w0 = packh2(WVAL(r,   k0  ), WVAL(r,   k0+1));
        unsigned w1 = packh2(WVAL(r+8, k0  ), WVAL(r+8, k0+1));
        unsigned w2 = packh2(WVAL(r,   k0+8), WVAL(r,   k0+9));
        unsigned w3 = packh2(WVAL(r+8, k0+8), WVAL(r+8, k0+9));
        #undef WVAL
        g_wfrag4[i4] = make_uint4(w0, w1, w2, w3);
        return;
    }

    int bc   = blockIdx.x;           // b*C + c
    int c    = bc % Cn;
    int base = bc * HW;

    if (tid < 49) wsm[tid] = dww[c*49 + tid];

    // phase 0: zero whole patch (float4 STS)
    {
        float4* p4 = reinterpret_cast<float4*>(&patch[0][0]);
        #pragma unroll
        for (int i = 0; i < 5; i++) {
            int idx = tid + i*256;
            if (idx < 1260) p4[idx] = make_float4(0.f, 0.f, 0.f, 0.f);
        }
    }
    __syncthreads();

    // phase 1: interior fill, vector LDG (x + hidden), scalar STS scatter
    #pragma unroll
    for (int i = 0; i < 4; i++) {
        int idx = tid + i*256;                // over 1024 float4 slots
        int gy = idx >> 4, gx4 = (idx & 15) << 2;
        int gi = base + gy*64 + gx4;
        float4 xv = __ldg(reinterpret_cast<const float4*>(x + gi));
        float4 hv = __ldg(reinterpret_cast<const float4*>(hid + gi));
        float* pr = &patch[gy + 3][gx4 + 3];
        pr[0] = xv.x + hv.x;
        pr[1] = xv.y + hv.y;
        pr[2] = xv.z + hv.z;
        pr[3] = xv.w + hv.w;
    }
    __syncthreads();

    float w[49];
    #pragma unroll
    for (int i = 0; i < 49; i++) w[i] = wsm[i];

    int ty = tid >> 4, tx = tid & 15;
    int oy0 = ty << 2, ox0 = tx << 2;
    float bias = dwb[c];
    float acc[4][4];
    #pragma unroll
    for (int j = 0; j < 4; j++)
        #pragma unroll
        for (int i = 0; i < 4; i++) acc[j][i] = bias;

    #pragma unroll
    for (int r = 0; r < 10; r++) {
        const float* pr = &patch[oy0 + r][ox0];
        float4 q0 = *reinterpret_cast<const float4*>(pr);
        float4 q1 = *reinterpret_cast<const float4*>(pr + 4);
        float4 q2 = *reinterpret_cast<const float4*>(pr + 8);
        float e[10] = {q0.x,q0.y,q0.z,q0.w, q1.x,q1.y,q1.z,q1.w, q2.x,q2.y};
        int lo = r - 6 < 0 ? 0 : r - 6;
        int hi = r < 3 ? r : 3;
        #pragma unroll
        for (int orow = 0; orow < 4; orow++) {
            if (orow < lo || orow > hi) continue;
            int wr = (r - orow)*7;
            #pragma unroll
            for (int kx = 0; kx < 7; kx++) {
                float wv = w[wr + kx];
                acc[orow][0] += wv*e[kx];   acc[orow][1] += wv*e[kx+1];
                acc[orow][2] += wv*e[kx+2]; acc[orow][3] += wv*e[kx+3];
            }
        }
    }

    float s = 0.f, s2 = 0.f;
    #pragma unroll
    for (int j = 0; j < 4; j++) {
        unsigned h0 = packh2(acc[j][0], acc[j][1]);
        unsigned h1 = packh2(acc[j][2], acc[j][3]);
        *reinterpret_cast<uint2*>(g_zch + base + (oy0+j)*64 + ox0) =
            make_uint2(h0, h1);
        #pragma unroll
        for (int i = 0; i < 4; i++) {
            s += acc[j][i]; s2 += acc[j][i]*acc[j][i];
        }
    }
    #pragma unroll
    for (int o = 16; o > 0; o >>= 1) {
        s  += __shfl_xor_sync(~0u, s,  o);
        s2 += __shfl_xor_sync(~0u, s2, o);
    }
    if ((tid & 31) == 0) { redsum[tid>>5] = s; redsq[tid>>5] = s2; }
    __syncthreads();
    if (tid == 0) {
        float S = 0.f, S2 = 0.f;
        #pragma unroll
        for (int i = 0; i < 8; i++) { S += redsum[i]; S2 += redsq[i]; }
        g_part[bc*2] = S; g_part[bc*2 + 1] = S2;
    }
}

// ---------------------------------------------------------------------------
// Kernel 2: finalize GN stats (48 channel partials per group)
// ---------------------------------------------------------------------------
__global__ __launch_bounds__(64) void stats_kernel()
{
    __shared__ float ss[64], sq[64];
    int gidx = blockIdx.x;
    int b = gidx >> 2, g = gidx & 3;
    int base = (b*Cn + g*CPG) * 2;
    int tid = threadIdx.x;
    float a = 0.f, q = 0.f;
    if (tid < 48) { a = g_part[base + tid*2]; q = g_part[base + tid*2 + 1]; }
    ss[tid] = a; sq[tid] = q;
    __syncthreads();
    for (int st = 32; st > 0; st >>= 1) {
        if (tid < st) { ss[tid] += ss[tid+st]; sq[tid] += sq[tid+st]; }
        __syncthreads();
    }
    if (tid == 0) {
        float inv = 1.0f / (float)NGRP;
        float mu  = ss[0] * inv;
        float var = sq[0] * inv - mu*mu;
        g_mu[gidx]   = mu;
        g_rstd[gidx] = rsqrtf(var + 1e-5f);
    }
}

// ---------------------------------------------------------------------------
// Kernel 3: fp16 m16n8k16 GEMM, 64-px x 12 segs of 64 rows, target 5 CTAs/SM.
// 6-pass staging (32 k-rows each), 2-phase epilogue (32 rows each).
// smem map:  [0, 24576)       znp fp16 fragment pairs
//            [24576, 36864)   3x 4KB k32 weight chunk ring
//            [36864, 45568)   zs fp32 staging [32][68] / epilogue [32r][68px]
// ---------------------------------------------------------------------------
#define WB_OFF  24576
#define WBUFSZ  4096
#define ZS_OFF  36864
#define EPI_OFF 36864
#define EPISTR  68
#define GSMEM   45568

__global__ __launch_bounds__(256,5) void gemm_kernel(
    const float* __restrict__ ctx, const float* __restrict__ cell,
    const float* __restrict__ pwb, float* __restrict__ out)
{
    extern __shared__ __align__(16) char smem[];
    int tid = threadIdx.x;
    int b   = blockIdx.x >> 6;
    int hw0 = (blockIdx.x & 63) << 6;
    int wid = tid >> 5, l = tid & 31;
    int g = l >> 2, t4 = l & 3;
    int wm = wid & 3, wn = wid >> 2;

    auto issue_chunk = [&](int n){
        const uint4* src = g_wfrag4 + n*256 + tid;
        unsigned sa = smem_u32(smem + WB_OFF + (n % 3)*WBUFSZ + tid*16);
        asm volatile("cp.async.cg.shared.global [%0], [%1], 16;"
                     :: "r"(sa), "l"(src));
        asm volatile("cp.async.commit_group;" ::: "memory");
    };
    issue_chunk(0);
    issue_chunk(1);

    // ---- 6-pass staging: GN/FiLM fused, fp16 fragment-pair packing ----
    const __half* zc = g_zch + (size_t)b*CHW + hw0;
    const float* cs = ctx + (size_t)b*2*CHW + hw0;
    float* zs = reinterpret_cast<float*>(smem + ZS_OFF);
    #pragma unroll 1
    for (int pass = 0; pass < 6; pass++) {
        int kbase = pass*32;
        #pragma unroll
        for (int i = 0; i < 2; i++) {
            int idx = tid + i*256;               // over 32*16 float4 slots
            int k = idx >> 4, p4 = (idx & 15) << 2;
            int kg = kbase + k;
            uint2 hv = __ldg(reinterpret_cast<const uint2*>(
                             zc + (size_t)kg*HW + p4));
            float2 f0 = __half22float2(*reinterpret_cast<__half2*>(&hv.x));
            float2 f1 = __half22float2(*reinterpret_cast<__half2*>(&hv.y));
            float4 sc = __ldg(reinterpret_cast<const float4*>(
                              cs + (size_t)kg*HW + p4));
            float4 bi = __ldg(reinterpret_cast<const float4*>(
                              cs + (size_t)(kg + Cn)*HW + p4));
            int gi = (b << 2) + ((kg*683) >> 15);
            float mu = g_mu[gi], rs = g_rstd[gi];
            float4 o;
            o.x = (f0.x - mu)*rs*(1.0f + sc.x) + bi.x;
            o.y = (f0.y - mu)*rs*(1.0f + sc.y) + bi.y;
            o.z = (f1.x - mu)*rs*(1.0f + sc.z) + bi.z;
            o.w = (f1.y - mu)*rs*(1.0f + sc.w) + bi.w;
            *reinterpret_cast<float4*>(zs + k*68 + p4) = o;
        }
        __syncthreads();
        {
            int px = tid >> 2, tt = tid & 3;
            #pragma unroll
            for (int cc = 0; cc < 2; cc++) {
                int c = pass*2 + cc;
                int k0 = cc*16 + tt*2;            // local k in zs
                float z0 = zs[ k0   *68 + px];
                float z1 = zs[(k0+1)*68 + px];
                float z2 = zs[(k0+8)*68 + px];
                float z3 = zs[(k0+9)*68 + px];
                *reinterpret_cast<uint2*>(smem + ((c*64 + px)*4 + tt)*8) =
                    make_uint2(packh2(z0, z1), packh2(z2, z3));
            }
        }
        __syncthreads();
    }

    float D[4][4];
    #pragma unroll
    for (int j = 0; j < 4; j++)
        #pragma unroll
        for (int q = 0; q < 4; q++) D[j][q] = 0.f;

    for (int seg = 0; seg < 12; seg++) {
        #pragma unroll 1
        for (int c32 = 0; c32 < 6; c32++) {
            int gc = seg*6 + c32;
            if (gc < 71)
                asm volatile("cp.async.wait_group 1;" ::: "memory");
            else
                asm volatile("cp.async.wait_group 0;" ::: "memory");
            __syncthreads();
            if (gc + 2 < 72) issue_chunk(gc + 2);

            const char* wb = smem + WB_OFF + (gc % 3)*WBUFSZ;
            #pragma unroll
            for (int h = 0; h < 2; h++) {
                int c16 = c32*2 + h;
                uint2 Bf[4];
                #pragma unroll
                for (int tn = 0; tn < 4; tn++) {
                    int p = wn*32 + tn*8 + g;
                    Bf[tn] = *reinterpret_cast<const uint2*>(
                                smem + ((c16*64 + p)*4 + t4)*8);
                }
                uint4 Af = *reinterpret_cast<const uint4*>(
                            wb + h*2048 + (wm*32 + l)*16);
                #pragma unroll
                for (int tn = 0; tn < 4; tn++)
                    mma_f16(D[tn], Af, Bf[tn]);
            }
        }

        // ---- epilogue for seg (16 ch x 64 px): 2 phases of 32 rows ----
        {
            float* ep = reinterpret_cast<float*>(smem + EPI_OFF);
            #pragma unroll 1
            for (int p = 0; p < 2; p++) {
                if ((wm >> 1) == p) {
                    int lr = (wm & 1)*16 + g;
                    #pragma unroll
                    for (int tn = 0; tn < 4; tn++) {
                        int px = wn*32 + tn*8 + 2*t4;
                        *reinterpret_cast<float2*>(ep +  lr     *EPISTR + px) =
                            make_float2(D[tn][0], D[tn][1]);
                        *reinterpret_cast<float2*>(ep + (lr + 8)*EPISTR + px) =
                            make_float2(D[tn][2], D[tn][3]);
                    }
                }
                __syncthreads();

                int lc  = tid >> 5;           // 0..7 local channel in phase
                int px2 = (tid & 31) << 1;    // 2 px each
                int ch  = seg*16 + p*8 + lc;
                float bfc = __ldg(pwb + ch),       bic = __ldg(pwb + 192 + ch);
                float bgc = __ldg(pwb + 384 + ch), boc = __ldg(pwb + 576 + ch);
                float2 ga[4];
                #pragma unroll
                for (int gate = 0; gate < 4; gate++)
                    ga[gate] = *reinterpret_cast<const float2*>(
                                   ep + (lc*4 + gate)*EPISTR + px2);
                size_t gbase = (size_t)b*CHW + (size_t)ch*HW + hw0 + px2;
                float2 cellv = __ldg(reinterpret_cast<const float2*>(
                                     cell + gbase));
                float cold[2] = {cellv.x, cellv.y};
                float gaf[4][2] = {{ga[0].x, ga[0].y}, {ga[1].x, ga[1].y},
                                   {ga[2].x, ga[2].y}, {ga[3].x, ga[3].y}};
                float hn[2], cn[2];
                #pragma unroll
                for (int j = 0; j < 2; j++) {
                    float fv = gaf[0][j] + bfc, iv = gaf[1][j] + bic;
                    float gg = gaf[2][j] + bgc, ov = gaf[3][j] + boc;
                    float cv = sigm_f(fv)*cold[j] + sigm_f(iv)*tanh_f(gg);
                    cn[j] = cv;
                    hn[j] = sigm_f(ov) * gelu_exact(cv);
                }
                *reinterpret_cast<float2*>(out + gbase) =
                    make_float2(hn[0], hn[1]);
                *reinterpret_cast<float2*>(out + NPIX + gbase) =
                    make_float2(cn[0], cn[1]);
                __syncthreads();
            }
        }
        #pragma unroll
        for (int j = 0; j < 4; j++)
            #pragma unroll
            for (int q = 0; q < 4; q++) D[j][q] = 0.f;
    }
}

// ---------------------------------------------------------------------------
extern "C" void kernel_launch(void* const* d_in, const int* in_sizes, int n_in,
                              void* d_out, int out_size)
{
    const float* x      = (const float*)d_in[0];
    const float* hidden = (const float*)d_in[1];
    const float* cell   = (const float*)d_in[2];
    const float* ctx    = (const float*)d_in[3];
    const float* dww    = (const float*)d_in[4];
    const float* dwb    = (const float*)d_in[5];
    const float* pw     = (const float*)d_in[6];
    const float* pwb    = (const float*)d_in[7];
    float* out = (float*)d_out;

    cudaFuncSetAttribute(gemm_kernel,
                         cudaFuncAttributeMaxDynamicSharedMemorySize, GSMEM);

    conv_kernel<<<Bn*Cn + 72, 256>>>(x, hidden, dww, dwb, pw);
    stats_kernel<<<64, 64>>>();
    gemm_kernel<<<1024, 256, GSMEM>>>(ctx, cell, pwb, out);
}

// round 17
// speedup vs baseline: 1.0675x; 1.0675x over previous
#include <cuda_runtime.h>
#include <cuda_fp16.h>
#include <math.h>

#define Bn 16
#define Cn 192
#define HW 4096
#define CHW (Cn*HW)          // 786432
#define NPIX (Bn*CHW)        // 12582912
#define CPG 48
#define NGRP (CPG*HW)        // 196608

// Scratch (device globals: allocation-free rule)
__device__ __half g_zch[NPIX];           // depthwise conv output (fp16)
__device__ uint4 g_wfrag4[18432];        // fp16 fragment-packed weights
__device__ float g_part[Bn*Cn*2];        // per-channel (sum, sumsq)
__device__ float g_mu[64];
__device__ float g_rstd[64];

__device__ __forceinline__ unsigned smem_u32(const void* p){
    unsigned a;
    asm("{ .reg .u64 t; cvta.to.shared.u64 t, %1; cvt.u32.u64 %0, t; }"
        : "=r"(a) : "l"(p));
    return a;
}
__device__ __forceinline__ unsigned packh2(float lo, float hi){
    __half2 h = __floats2half2_rn(lo, hi);
    return *reinterpret_cast<unsigned*>(&h);
}
__device__ __forceinline__ float sigm_f(float v){
    return __fdividef(1.0f, 1.0f + __expf(-v));
}
__device__ __forceinline__ float tanh_f(float v){
    float a = __expf(2.0f*v);
    return 1.0f - __fdividef(2.0f, a + 1.0f);
}
__device__ __forceinline__ float gelu_exact(float v){
    return 0.5f*v*(1.0f + erff(v*0.70710678118654752f));
}
// fp16 m16n8k16 MMA, fp32 accumulate
__device__ __forceinline__ void mma_f16(float d[4], uint4 A, uint2 B){
    asm volatile("mma.sync.aligned.m16n8k16.row.col.f32.f16.f16.f32 "
        "{%0,%1,%2,%3}, {%4,%5,%6,%7}, {%8,%9}, {%0,%1,%2,%3};"
        : "+f"(d[0]), "+f"(d[1]), "+f"(d[2]), "+f"(d[3])
        : "r"(A.x), "r"(A.y), "r"(A.z), "r"(A.w), "r"(B.x), "r"(B.y));
}

// ---------------------------------------------------------------------------
// Kernel 1: conv (blocks < Bn*Cn) + weight packing (last 72 blocks).
// Conv: one block per (b,c) channel, 4x4 outputs/thread, fp16 out, fp32 stats.
// (R15 version — measured 38us including packing)
// ---------------------------------------------------------------------------
__global__ __launch_bounds__(256) void conv_kernel(
    const float* __restrict__ x, const float* __restrict__ hid,
    const float* __restrict__ dww, const float* __restrict__ dwb,
    const float* __restrict__ pw)
{
    __shared__ __align__(16) float patch[70][72];   // 20160 B, px = gx+3
    __shared__ float wsm[49];
    __shared__ float redsum[8], redsq[8];

    int tid  = threadIdx.x;

    // --- weight-packing path (blocks Bn*Cn .. Bn*Cn+71) ---
    if (blockIdx.x >= Bn*Cn) {
        int i4 = (blockIdx.x - Bn*Cn)*256 + tid;     // 0..18431
        int chunk = i4 >> 8, j = i4 & 255;
        int seg12 = chunk / 6, c32 = chunk - seg12*6;
        int h = j >> 7, slot = (j >> 5) & 3, l = j & 31;
        int g = l >> 2, t = l & 3;
        int r  = seg12*64 + slot*16 + g;
        int k0 = c32*32 + h*16 + 2*t;
        #define WVAL(rr, kk) pw[(((rr) & 3)*192 + ((rr) >> 2))*192 + (kk)]
        unsigned w0 = packh2(WVAL(r,   k0  ), WVAL(r,   k0+1));
        unsigned w1 = packh2(WVAL(r+8, k0  ), WVAL(r+8, k0+1));
        unsigned w2 = packh2(WVAL(r,   k0+8), WVAL(r,   k0+9));
        unsigned w3 = packh2(WVAL(r+8, k0+8), WVAL(r+8, k0+9));
        #undef WVAL
        g_wfrag4[i4] = make_uint4(w0, w1, w2, w3);
        return;
    }

    int bc   = blockIdx.x;           // b*C + c
    int c    = bc % Cn;
    int base = bc * HW;

    if (tid < 49) wsm[tid] = dww[c*49 + tid];

    // phase 0: zero whole patch (float4 STS)
    {
        float4* p4 = reinterpret_cast<float4*>(&patch[0][0]);
        #pragma unroll
        for (int i = 0; i < 5; i++) {
            int idx = tid + i*256;
            if (idx < 1260) p4[idx] = make_float4(0.f, 0.f, 0.f, 0.f);
        }
    }
    __syncthreads();

    // phase 1: interior fill, vector LDG (x + hidden), scalar STS scatter
    #pragma unroll
    for (int i = 0; i < 4; i++) {
        int idx = tid + i*256;                // over 1024 float4 slots
        int gy = idx >> 4, gx4 = (idx & 15) << 2;
        int gi = base + gy*64 + gx4;
        float4 xv = __ldg(reinterpret_cast<const float4*>(x + gi));
        float4 hv = __ldg(reinterpret_cast<const float4*>(hid + gi));
        float* pr = &patch[gy + 3][gx4 + 3];
        pr[0] = xv.x + hv.x;
        pr[1] = xv.y + hv.y;
        pr[2] = xv.z + hv.z;
        pr[3] = xv.w + hv.w;
    }
    __syncthreads();

    float w[49];
    #pragma unroll
    for (int i = 0; i < 49; i++) w[i] = wsm[i];

    int ty = tid >> 4, tx = tid & 15;
    int oy0 = ty << 2, ox0 = tx << 2;
    float bias = dwb[c];
    float acc[4][4];
    #pragma unroll
    for (int j = 0; j < 4; j++)
        #pragma unroll
        for (int i = 0; i < 4; i++) acc[j][i] = bias;

    #pragma unroll
    for (int r = 0; r < 10; r++) {
        const float* pr = &patch[oy0 + r][ox0];
        float4 q0 = *reinterpret_cast<const float4*>(pr);
        float4 q1 = *reinterpret_cast<const float4*>(pr + 4);
        float4 q2 = *reinterpret_cast<const float4*>(pr + 8);
        float e[10] = {q0.x,q0.y,q0.z,q0.w, q1.x,q1.y,q1.z,q1.w, q2.x,q2.y};
        int lo = r - 6 < 0 ? 0 : r - 6;
        int hi = r < 3 ? r : 3;
        #pragma unroll
        for (int orow = 0; orow < 4; orow++) {
            if (orow < lo || orow > hi) continue;
            int wr = (r - orow)*7;
            #pragma unroll
            for (int kx = 0; kx < 7; kx++) {
                float wv = w[wr + kx];
                acc[orow][0] += wv*e[kx];   acc[orow][1] += wv*e[kx+1];
                acc[orow][2] += wv*e[kx+2]; acc[orow][3] += wv*e[kx+3];
            }
        }
    }

    float s = 0.f, s2 = 0.f;
    #pragma unroll
    for (int j = 0; j < 4; j++) {
        unsigned h0 = packh2(acc[j][0], acc[j][1]);
        unsigned h1 = packh2(acc[j][2], acc[j][3]);
        *reinterpret_cast<uint2*>(g_zch + base + (oy0+j)*64 + ox0) =
            make_uint2(h0, h1);
        #pragma unroll
        for (int i = 0; i < 4; i++) {
            s += acc[j][i]; s2 += acc[j][i]*acc[j][i];
        }
    }
    #pragma unroll
    for (int o = 16; o > 0; o >>= 1) {
        s  += __shfl_xor_sync(~0u, s,  o);
        s2 += __shfl_xor_sync(~0u, s2, o);
    }
    if ((tid & 31) == 0) { redsum[tid>>5] = s; redsq[tid>>5] = s2; }
    __syncthreads();
    if (tid == 0) {
        float S = 0.f, S2 = 0.f;
        #pragma unroll
        for (int i = 0; i < 8; i++) { S += redsum[i]; S2 += redsq[i]; }
        g_part[bc*2] = S; g_part[bc*2 + 1] = S2;
    }
}

// ---------------------------------------------------------------------------
// Kernel 2: finalize GN stats (48 channel partials per group)
// ---------------------------------------------------------------------------
__global__ __launch_bounds__(64) void stats_kernel()
{
    __shared__ float ss[64], sq[64];
    int gidx = blockIdx.x;
    int b = gidx >> 2, g = gidx & 3;
    int base = (b*Cn + g*CPG) * 2;
    int tid = threadIdx.x;
    float a = 0.f, q = 0.f;
    if (tid < 48) { a = g_part[base + tid*2]; q = g_part[base + tid*2 + 1]; }
    ss[tid] = a; sq[tid] = q;
    __syncthreads();
    for (int st = 32; st > 0; st >>= 1) {
        if (tid < st) { ss[tid] += ss[tid+st]; sq[tid] += sq[tid+st]; }
        __syncthreads();
    }
    if (tid == 0) {
        float inv = 1.0f / (float)NGRP;
        float mu  = ss[0] * inv;
        float var = sq[0] * inv - mu*mu;
        g_mu[gidx]   = mu;
        g_rstd[gidx] = rsqrtf(var + 1e-5f);
    }
}

// ---------------------------------------------------------------------------
// Kernel 3: fp16 m16n8k16 GEMM — exact R14 structure (measured 129.1us):
// 64-px x 12 segs of 64 rows, 4 CTAs/SM, 3-pass staging, single-shot epilogue.
// smem map:  [0, 24576)       znp fp16 fragment pairs
//            [24576, 36864)   3x 4KB k32 weight chunk ring
//            [36864, 54272)   zs fp32 staging [64][68] / epilogue [64r][68px]
// ---------------------------------------------------------------------------
#define WB_OFF  24576
#define WBUFSZ  4096
#define ZS_OFF  36864
#define EPI_OFF 36864
#define EPISTR  68
#define GSMEM   54272

__global__ __launch_bounds__(256,4) void gemm_kernel(
    const float* __restrict__ ctx, const float* __restrict__ cell,
    const float* __restrict__ pwb, float* __restrict__ out)
{
    extern __shared__ __align__(16) char smem[];
    int tid = threadIdx.x;
    int b   = blockIdx.x >> 6;
    int hw0 = (blockIdx.x & 63) << 6;
    int wid = tid >> 5, l = tid & 31;
    int g = l >> 2, t4 = l & 3;
    int wm = wid & 3, wn = wid >> 2;

    auto issue_chunk = [&](int n){
        const uint4* src = g_wfrag4 + n*256 + tid;
        unsigned sa = smem_u32(smem + WB_OFF + (n % 3)*WBUFSZ + tid*16);
        asm volatile("cp.async.cg.shared.global [%0], [%1], 16;"
                     :: "r"(sa), "l"(src));
        asm volatile("cp.async.commit_group;" ::: "memory");
    };
    issue_chunk(0);
    issue_chunk(1);

    const __half* zc = g_zch + (size_t)b*CHW + hw0;
    const float* cs = ctx + (size_t)b*2*CHW + hw0;
    float* zs = reinterpret_cast<float*>(smem + ZS_OFF);
    #pragma unroll
    for (int pass = 0; pass < 3; pass++) {
        int kbase = pass*64;
        #pragma unroll
        for (int i = 0; i < 4; i++) {
            int idx = tid + i*256;
            int k = idx >> 4, p4 = (idx & 15) << 2;
            int kg = kbase + k;
            uint2 hv = __ldg(reinterpret_cast<const uint2*>(
                             zc + (size_t)kg*HW + p4));
            float2 f0 = __half22float2(*reinterpret_cast<__half2*>(&hv.x));
            float2 f1 = __half22float2(*reinterpret_cast<__half2*>(&hv.y));
            float4 sc = __ldg(reinterpret_cast<const float4*>(
                              cs + (size_t)kg*HW + p4));
            float4 bi = __ldg(reinterpret_cast<const float4*>(
                              cs + (size_t)(kg + Cn)*HW + p4));
            int gi = (b << 2) + ((kg*683) >> 15);
            float mu = g_mu[gi], rs = g_rstd[gi];
            float4 o;
            o.x = (f0.x - mu)*rs*(1.0f + sc.x) + bi.x;
            o.y = (f0.y - mu)*rs*(1.0f + sc.y) + bi.y;
            o.z = (f1.x - mu)*rs*(1.0f + sc.z) + bi.z;
            o.w = (f1.y - mu)*rs*(1.0f + sc.w) + bi.w;
            *reinterpret_cast<float4*>(zs + k*68 + p4) = o;
        }
        __syncthreads();
        {
            int px = tid >> 2, tt = tid & 3;
            #pragma unroll
            for (int cc = 0; cc < 4; cc++) {
                int c = pass*4 + cc;
                int k0 = cc*16 + tt*2;
                float z0 = zs[ k0   *68 + px];
                float z1 = zs[(k0+1)*68 + px];
                float z2 = zs[(k0+8)*68 + px];
                float z3 = zs[(k0+9)*68 + px];
                *reinterpret_cast<uint2*>(smem + ((c*64 + px)*4 + tt)*8) =
                    make_uint2(packh2(z0, z1), packh2(z2, z3));
            }
        }
        __syncthreads();
    }

    float D[4][4];
    #pragma unroll
    for (int j = 0; j < 4; j++)
        #pragma unroll
        for (int q = 0; q < 4; q++) D[j][q] = 0.f;

    for (int seg = 0; seg < 12; seg++) {
        #pragma unroll 1
        for (int c32 = 0; c32 < 6; c32++) {
            int gc = seg*6 + c32;
            if (gc < 71)
                asm volatile("cp.async.wait_group 1;" ::: "memory");
            else
                asm volatile("cp.async.wait_group 0;" ::: "memory");
            __syncthreads();
            if (gc + 2 < 72) issue_chunk(gc + 2);

            const char* wb = smem + WB_OFF + (gc % 3)*WBUFSZ;
            #pragma unroll
            for (int h = 0; h < 2; h++) {
                int c16 = c32*2 + h;
                uint2 Bf[4];
                #pragma unroll
                for (int tn = 0; tn < 4; tn++) {
                    int p = wn*32 + tn*8 + g;
                    Bf[tn] = *reinterpret_cast<const uint2*>(
                                smem + ((c16*64 + p)*4 + t4)*8);
                }
                uint4 Af = *reinterpret_cast<const uint4*>(
                            wb + h*2048 + (wm*32 + l)*16);
                #pragma unroll
                for (int tn = 0; tn < 4; tn++)
                    mma_f16(D[tn], Af, Bf[tn]);
            }
        }

        // ---- epilogue for seg (16 channels x 64 px), single transpose ----
        {
            float* ep = reinterpret_cast<float*>(smem + EPI_OFF);
            int lr = wm*16 + g;
            #pragma unroll
            for (int tn = 0; tn < 4; tn++) {
                int px = wn*32 + tn*8 + 2*t4;
                *reinterpret_cast<float2*>(ep +  lr     *EPISTR + px) =
                    make_float2(D[tn][0], D[tn][1]);
                *reinterpret_cast<float2*>(ep + (lr + 8)*EPISTR + px) =
                    make_float2(D[tn][2], D[tn][3]);
            }
            __syncthreads();

            int chl = tid >> 4;
            int pq  = tid & 15;
            int ch  = seg*16 + chl;
            float bfc = __ldg(pwb + ch),       bic = __ldg(pwb + 192 + ch);
            float bgc = __ldg(pwb + 384 + ch), boc = __ldg(pwb + 576 + ch);
            float ga[4][4];
            #pragma unroll
            for (int gate = 0; gate < 4; gate++)
                *reinterpret_cast<float4*>(ga[gate]) =
                    *reinterpret_cast<const float4*>(
                        ep + (chl*4 + gate)*EPISTR + pq*4);
            size_t gbase = (size_t)b*CHW + (size_t)ch*HW + hw0 + pq*4;
            float4 cellv = __ldg(reinterpret_cast<const float4*>(cell + gbase));
            float cold[4] = {cellv.x, cellv.y, cellv.z, cellv.w};
            float hn[4], cn[4];
            #pragma unroll
            for (int j = 0; j < 4; j++) {
                float fv = ga[0][j] + bfc, iv = ga[1][j] + bic;
                float gg = ga[2][j] + bgc, ov = ga[3][j] + boc;
                float cv = sigm_f(fv)*cold[j] + sigm_f(iv)*tanh_f(gg);
                cn[j] = cv;
                hn[j] = sigm_f(ov) * gelu_exact(cv);
            }
            *reinterpret_cast<float4*>(out + gbase) =
                make_float4(hn[0], hn[1], hn[2], hn[3]);
            *reinterpret_cast<float4*>(out + NPIX + gbase) =
                make_float4(cn[0], cn[1], cn[2], cn[3]);
        }
        #pragma unroll
        for (int j = 0; j < 4; j++)
            #pragma unroll
            for (int q = 0; q < 4; q++) D[j][q] = 0.f;
    }
}

// ---------------------------------------------------------------------------
extern "C" void kernel_launch(void* const* d_in, const int* in_sizes, int n_in,
                              void* d_out, int out_size)
{
    const float* x      = (const float*)d_in[0];
    const float* hidden = (const float*)d_in[1];
    const float* cell   = (const float*)d_in[2];
    const float* ctx    = (const float*)d_in[3];
    const float* dww    = (const float*)d_in[4];
    const float* dwb    = (const float*)d_in[5];
    const float* pw     = (const float*)d_in[6];
    const float* pwb    = (const float*)d_in[7];
    float* out = (float*)d_out;

    cudaFuncSetAttribute(gemm_kernel,
                         cudaFuncAttributeMaxDynamicSharedMemorySize, GSMEM);

    conv_kernel<<<Bn*Cn + 72, 256>>>(x, hidden, dww, dwb, pw);
    stats_kernel<<<64, 64>>>();
    gemm_kernel<<<1024, 256, GSMEM>>>(ctx, cell, pwb, out);
}